// round 2
// baseline (speedup 1.0000x reference)
#include <cuda_runtime.h>

// PositionalEncoding: out[b,s,d] = x[b,s,d] + pe[s,d]
//   pe[s,d] = sin(s / 10000^((d/2)/4096)) if d even else cos(...)
// Shapes fixed by the problem: B=8, S=4096, D=1024, fp32.
//
// Strategy: one thread per float4 of the (S,D) pe plane. Compute the two
// (sin,cos) pairs once in registers, then stream all 8 batches through,
// reusing the pe registers. This makes the kernel purely DRAM-bound
// (256 MiB total traffic) with transcendental work divided by 8.

namespace {
constexpr int B = 8;
constexpr int S = 4096;
constexpr int D = 1024;
constexpr int PLANE4 = S * D / 4;      // float4 elements per batch plane = 1,048,576
constexpr int D4 = D / 4;              // 256 float4 per row
}

__global__ __launch_bounds__(256) void pe_add_kernel(const float4* __restrict__ x,
                                                     float4* __restrict__ out) {
    int idx = blockIdx.x * blockDim.x + threadIdx.x;   // [0, PLANE4)
    if (idx >= PLANE4) return;

    int pos = idx >> 8;          // idx / D4
    int c4  = idx & (D4 - 1);    // float4 column within row
    // d = 4*c4 .. 4*c4+3 ;  k = d>>1  ->  k0 = 2*c4 (for d0,d1), k1 = 2*c4+1 (for d2,d3)
    float k0 = (float)(2 * c4);
    float k1 = k0 + 1.0f;
    float fpos = (float)pos;

    // angle = pos / 10000^(k/4096)  (faithful to reference: denominator is S)
    float e0 = powf(10000.0f, k0 * (1.0f / 4096.0f));
    float e1 = powf(10000.0f, k1 * (1.0f / 4096.0f));
    float a0 = fpos / e0;
    float a1 = fpos / e1;

    float s0, c0, s1, c1;
    sincosf(a0, &s0, &c0);
    sincosf(a1, &s1, &c1);
    // d even -> sin, d odd -> cos
    float4 pe = make_float4(s0, c0, s1, c1);

#pragma unroll
    for (int b = 0; b < B; ++b) {
        size_t off = (size_t)b * PLANE4 + (size_t)idx;
        float4 v = x[off];
        v.x += pe.x;
        v.y += pe.y;
        v.z += pe.z;
        v.w += pe.w;
        out[off] = v;
    }
}

extern "C" void kernel_launch(void* const* d_in, const int* in_sizes, int n_in,
                              void* d_out, int out_size) {
    (void)in_sizes; (void)n_in; (void)out_size;
    const float4* x = (const float4*)d_in[0];
    float4* out = (float4*)d_out;

    int threads = 256;
    int blocks = PLANE4 / threads;   // 4096 blocks
    pe_add_kernel<<<blocks, threads>>>(x, out);
}